// round 11
// baseline (speedup 1.0000x reference)
#include <cuda_runtime.h>
#include <cuda_fp16.h>

// DigitCaps routing:
//   x [128,1024,16], W [1,16,1024,16,16], B [16,1,1024] -> out [128,16,16] (fp32)
//
// R11 = DIAGNOSTIC ROUND: identical kernels to R10 (best: 102.4us), but
// k1_uhat is launched TWICE (idempotent, deterministic). Measured dur_us
// = 102.4 + k1_time, giving the first exact k1/k2a split of this session.

#define BATCH  128
#define NCAPS  16
#define INCAPS 1024
#define DIMC   16
#define COEF   0.25f

#define K1_CB     8
#define K1_NCBLK  128
#define K2_CT     32
#define K2_SPLIT  16
#define K2_TILES  2    // 1024 / (32*16)

#define RED_STRIDE 289   // u32 row stride for red[c_loc][...]
#define XS_STRIDE  132   // float row stride for xs[b_loc][...] (128 + 4 pad)

typedef unsigned long long u64;
typedef unsigned int u32;

__device__ __forceinline__ u64 f2fma(u64 a, u64 b, u64 c) {
    u64 d;
    asm("fma.rn.f32x2 %0, %1, %2, %3;" : "=l"(d) : "l"(a), "l"(b), "l"(c));
    return d;
}

__device__ __forceinline__ u32 h2_bits(__half2 h) {
    union { __half2 h; u32 u; } cv;
    cv.h = h;
    return cv.u;
}

// scratch
__device__ __half g_uhat[(size_t)BATCH * NCAPS * INCAPS * DIMC];    // [b][n][c][d] fp16, 64 MB
__device__ float  g_part[(size_t)K1_NCBLK * BATCH * NCAPS * DIMC];  // [cblk][b][n*16+d], 16 MB
__device__ float  g_usum[(size_t)BATCH * NCAPS * DIMC];             // 128 KB
__device__ float  g_spart[(size_t)K2_SPLIT * BATCH * NCAPS * DIMC]; // 2 MB

// ---------------------------------------------------------------------------
// Kernel 1: grid (128 cblk, 16 n), 256 threads = 8 warps.  (identical to R10)
// ---------------------------------------------------------------------------
__global__ __launch_bounds__(256) void k1_uhat(const float* __restrict__ x,
                                               const float* __restrict__ W) {
    __shared__ float ws[2048];                 // [8c][16d][16i], 8 KB
    __shared__ float xs[32 * XS_STRIDE];       // [32b][8c*16i + pad], 16.9 KB
    __shared__ u32   red[8 * RED_STRIDE];      // [c_loc][l*9+dp] half2, 9.25 KB

    const int t = threadIdx.x;
    const int w = t >> 5;        // c-local = warp id (0..7)
    const int l = t & 31;        // b lane
    const int cblk = blockIdx.x;
    const int n    = blockIdx.y;
    const int c0   = cblk * K1_CB;

    // --- load W tile (512 float4, linear, coalesced, conflict-free)
    const float4* Wg4 = (const float4*)W;
    float4* ws4 = (float4*)ws;
    const int wb4 = n * 65536 + c0 * 64;
    ws4[t]       = Wg4[wb4 + t];
    ws4[t + 256] = Wg4[wb4 + t + 256];

    const float4* xg4 = (const float4*)x;
    uint4* ug = (uint4*)g_uhat;
    const float* wsc = ws + w * 256;

    float4 P[4];
#pragma unroll
    for (int k = 0; k < 4; k++) {
        int q = t + 256 * k;
        P[k] = xg4[(q >> 5) * 4096 + c0 * 4 + (q & 31)];
    }

    union F4Q { float4 f[4]; u64 q[8]; };

#pragma unroll
    for (int bt = 0; bt < 4; bt++) {
        const int b0 = bt * 32;

#pragma unroll
        for (int k = 0; k < 4; k++) {
            int q = t + 256 * k;
            *(float4*)&xs[(q >> 5) * XS_STRIDE + (q & 31) * 4] = P[k];
        }
        __syncthreads();

        if (bt < 3) {
#pragma unroll
            for (int k = 0; k < 4; k++) {
                int q = t + 256 * k;
                P[k] = xg4[(b0 + 32 + (q >> 5)) * 4096 + c0 * 4 + (q & 31)];
            }
        }

        F4Q Xc;
#pragma unroll
        for (int k = 0; k < 4; k++)
            Xc.f[k] = *(const float4*)&xs[l * XS_STRIDE + w * 16 + k * 4];

        u32 out[8];
#pragma unroll
        for (int dp = 0; dp < 8; dp++) {
            float vh0, vh1;
#pragma unroll
            for (int h = 0; h < 2; h++) {
                const int d = dp * 2 + h;
                F4Q Wv;
                Wv.f[0] = *(const float4*)&wsc[d * 16 + 0];
                Wv.f[1] = *(const float4*)&wsc[d * 16 + 4];
                Wv.f[2] = *(const float4*)&wsc[d * 16 + 8];
                Wv.f[3] = *(const float4*)&wsc[d * 16 + 12];
                u64 sA = f2fma(Xc.q[0], Wv.q[0], 0ULL);
                u64 sB = f2fma(Xc.q[1], Wv.q[1], 0ULL);
                sA = f2fma(Xc.q[2], Wv.q[2], sA);
                sB = f2fma(Xc.q[3], Wv.q[3], sB);
                sA = f2fma(Xc.q[4], Wv.q[4], sA);
                sB = f2fma(Xc.q[5], Wv.q[5], sB);
                sA = f2fma(Xc.q[6], Wv.q[6], sA);
                sB = f2fma(Xc.q[7], Wv.q[7], sB);
                float2 fa = *(float2*)&sA;
                float2 fb = *(float2*)&sB;
                float v = (fa.x + fa.y) + (fb.x + fb.y);
                if (h == 0) vh0 = v; else vh1 = v;
            }
            out[dp] = h2_bits(__floats2half2_rn(vh0, vh1));
        }

#pragma unroll
        for (int q = 0; q < 8; q++) red[w * RED_STRIDE + l * 9 + q] = out[q];
        __syncthreads();

#pragma unroll
        for (int k = 0; k < 2; k++) {
            int q = t + 256 * k;
            int b_loc = q >> 4;
            int ch    = q & 15;
            int c_loc = ch >> 1;
            int dh    = ch & 1;
            const u32* rp = &red[c_loc * RED_STRIDE + b_loc * 9 + dh * 4];
            uint4 v = make_uint4(rp[0], rp[1], rp[2], rp[3]);
            size_t gi = ((size_t)((b0 + b_loc) * 16 + n) * 1024 + c0 + c_loc) * 2 + dh;
            ug[gi] = v;
        }

        {
            const int b2 = t >> 3, dp2 = t & 7;
            float s0 = 0.f, s1 = 0.f;
#pragma unroll
            for (int w2 = 0; w2 < 8; w2++) {
                __half2 hv = *(__half2*)&red[w2 * RED_STRIDE + b2 * 9 + dp2];
                float2 f = __half22float2(hv);
                s0 += f.x; s1 += f.y;
            }
            *(float2*)&g_part[cblk * 32768 + (b0 + b2) * 256 + n * 16 + dp2 * 2] =
                make_float2(s0, s1);
        }
    }
}

// ---------------------------------------------------------------------------
// k_usum: grid 128 (b), 256 threads
// ---------------------------------------------------------------------------
__global__ __launch_bounds__(256) void k_usum() {
    const int t = threadIdx.x, b = blockIdx.x;
    const float* p = g_part + b * 256 + t;
    float a0 = 0, a1 = 0, a2 = 0, a3 = 0, a4 = 0, a5 = 0, a6 = 0, a7 = 0;
#pragma unroll
    for (int k = 0; k < K1_NCBLK; k += 8) {
        a0 += p[(size_t)(k + 0) * 32768];
        a1 += p[(size_t)(k + 1) * 32768];
        a2 += p[(size_t)(k + 2) * 32768];
        a3 += p[(size_t)(k + 3) * 32768];
        a4 += p[(size_t)(k + 4) * 32768];
        a5 += p[(size_t)(k + 5) * 32768];
        a6 += p[(size_t)(k + 6) * 32768];
        a7 += p[(size_t)(k + 7) * 32768];
    }
    g_usum[b * 256 + t] = ((a0 + a1) + (a2 + a3)) + ((a4 + a5) + (a6 + a7));
}

// ---------------------------------------------------------------------------
// k2a: grid (128 b, 16 csplit), 256 threads, 2 tiles of 32 c.  (identical)
// ---------------------------------------------------------------------------
__global__ __launch_bounds__(256) void k2a_route(const float* __restrict__ Bb) {
    __shared__ uint4 uhs[16 * 97];
    __shared__ float sco[544];
    __shared__ float wbf[544];

    const int t  = threadIdx.x;
    const int b  = blockIdx.x;
    const int cs = blockIdx.y;

    const int sn = t >> 4, scs = t & 15;
    float ur[16];
#pragma unroll
    for (int j = 0; j < 16; j++) ur[j] = g_usum[b * 256 + sn * 16 + j];

    const int asp = t >> 6, an = (t >> 2) & 15, adq = t & 3;
    float sacc0 = 0, sacc1 = 0, sacc2 = 0, sacc3 = 0;

    const uint4* ug = (const uint4*)g_uhat;

    int ld_nn[4], ld_cl[4], ld_dh[4];
#pragma unroll
    for (int k = 0; k < 4; k++) {
        int flat = (t + 256 * k) * 8;
        ld_nn[k] = flat >> 9;
        ld_cl[k] = (flat >> 4) & 31;
        ld_dh[k] = (flat >> 3) & 1;
    }

    uint4 pv[4];
    {
        const int cb = cs * 64;
#pragma unroll
        for (int k = 0; k < 4; k++)
            pv[k] = ug[((size_t)(b * 16 + ld_nn[k]) * 1024 + cb + ld_cl[k]) * 2 + ld_dh[k]];
    }

#pragma unroll
    for (int tile = 0; tile < K2_TILES; tile++) {
        const int cb = cs * 64 + tile * K2_CT;
        __syncthreads();

#pragma unroll
        for (int k = 0; k < 4; k++)
            uhs[ld_nn[k] * 97 + ld_cl[k] * 3 + ld_dh[k]] = pv[k];
        __syncthreads();

        if (tile + 1 < K2_TILES) {
            const int cbn = cb + K2_CT;
#pragma unroll
            for (int k = 0; k < 4; k++)
                pv[k] = ug[((size_t)(b * 16 + ld_nn[k]) * 1024 + cbn + ld_cl[k]) * 2 + ld_dh[k]];
        }

        // --- scores
#pragma unroll
        for (int p = 0; p < 2; p++) {
            int cx = scs + p * 16;
            uint4 ua = uhs[sn * 97 + cx * 3 + 0];
            uint4 ub = uhs[sn * 97 + cx * 3 + 1];
            const __half2* ha = (const __half2*)&ua;
            const __half2* hb = (const __half2*)&ub;
            float dot = 0.f;
#pragma unroll
            for (int j = 0; j < 4; j++) {
                float2 fa = __half22float2(ha[j]);
                float2 fb = __half22float2(hb[j]);
                dot += fa.x * ur[2 * j] + fa.y * ur[2 * j + 1];
                dot += fb.x * ur[8 + 2 * j] + fb.y * ur[9 + 2 * j];
            }
            sco[cx * 17 + sn] = COEF * dot;
        }
        __syncthreads();

        // --- softmax over n + add B
        if (t < 32) {
            int cx = t;
            float v[16];
            float m = -1e30f;
#pragma unroll
            for (int nn = 0; nn < 16; nn++) { v[nn] = sco[cx * 17 + nn]; m = fmaxf(m, v[nn]); }
            float s = 0.f;
#pragma unroll
            for (int nn = 0; nn < 16; nn++) { v[nn] = expf(v[nn] - m); s += v[nn]; }
            float inv = 1.0f / s;
#pragma unroll
            for (int nn = 0; nn < 16; nn++)
                wbf[cx * 17 + nn] = v[nn] * inv + Bb[nn * 1024 + cb + cx];
        }
        __syncthreads();

        // --- weighted accumulate
        const __half2* uh2 = (const __half2*)uhs;
#pragma unroll
        for (int j = 0; j < 8; j++) {
            int cc2 = asp * 8 + j;
            float wv = wbf[cc2 * 17 + an];
            int h2i = (an * 97 + cc2 * 3) * 4 + adq * 2;
            float2 f0 = __half22float2(uh2[h2i]);
            float2 f1 = __half22float2(uh2[h2i + 1]);
            sacc0 += wv * f0.x; sacc1 += wv * f0.y;
            sacc2 += wv * f1.x; sacc3 += wv * f1.y;
        }
    }
    __syncthreads();

    float* spart = (float*)uhs;
    *(float4*)&spart[asp * 256 + an * 16 + adq * 4] = make_float4(sacc0, sacc1, sacc2, sacc3);
    __syncthreads();
    g_spart[cs * 32768 + b * 256 + t] =
        spart[t] + spart[256 + t] + spart[512 + t] + spart[768 + t];
}

// ---------------------------------------------------------------------------
// k2b: reduce 16 csplits, squash, write out
// ---------------------------------------------------------------------------
__global__ __launch_bounds__(256) void k2b_finish(float* __restrict__ out) {
    __shared__ float sfin[256];
    __shared__ float scale[16];
    const int t = threadIdx.x, b = blockIdx.x;

    const float* p = g_spart + b * 256 + t;
    float a0 = 0, a1 = 0, a2 = 0, a3 = 0;
#pragma unroll
    for (int k = 0; k < K2_SPLIT; k += 4) {
        a0 += p[(k + 0) * 32768];
        a1 += p[(k + 1) * 32768];
        a2 += p[(k + 2) * 32768];
        a3 += p[(k + 3) * 32768];
    }
    sfin[t] = (a0 + a1) + (a2 + a3);
    __syncthreads();

    if (t < 16) {
        float sq = 0.f;
#pragma unroll
        for (int d = 0; d < 16; d++) { float z = sfin[t * 16 + d]; sq += z * z; }
        float norm = sqrtf(sq);
        scale[t] = (1.0f - expf(-norm)) * rsqrtf(sq + 1e-8f);
    }
    __syncthreads();

    out[b * 256 + t] = scale[t >> 4] * sfin[t];
}

// ---------------------------------------------------------------------------
extern "C" void kernel_launch(void* const* d_in, const int* in_sizes, int n_in,
                              void* d_out, int out_size) {
    const float* x = (const float*)d_in[0];
    const float* W = (const float*)d_in[1];
    const float* B = (const float*)d_in[2];
    float* out = (float*)d_out;

    // DIAGNOSTIC: k1 launched twice (idempotent). dur_us - 102.4 == k1 time.
    k1_uhat<<<dim3(K1_NCBLK, NCAPS), 256>>>(x, W);
    k1_uhat<<<dim3(K1_NCBLK, NCAPS), 256>>>(x, W);
    k_usum<<<BATCH, 256>>>();
    k2a_route<<<dim3(BATCH, K2_SPLIT), 256>>>(B);
    k2b_finish<<<BATCH, 256>>>(out);
}

// round 12
// speedup vs baseline: 1.7566x; 1.7566x over previous
#include <cuda_runtime.h>
#include <cuda_fp16.h>

// DigitCaps routing:
//   x [128,1024,16], W [1,16,1024,16,16], B [16,1,1024] -> out [128,16,16] (fp32)
// Measured split (R11 bisect): k1 ~59.5us, k2a 29.4us, k_usum ~8.5us, k2b 5us.

#define BATCH  128
#define NCAPS  16
#define INCAPS 1024
#define DIMC   16
#define COEF   0.25f

#define K1_CB     8
#define K1_NCBLK  128
#define K2_CT     32
#define K2_SPLIT  16
#define K2_TILES  2    // 1024 / (32*16)

#define RED_STRIDE 289   // u32 row stride for red[c_loc][...]
#define XS_STRIDE  132   // float row stride for xs[b_loc][...] (128 + 4 pad)

typedef unsigned long long u64;
typedef unsigned int u32;

__device__ __forceinline__ u64 f2fma(u64 a, u64 b, u64 c) {
    u64 d;
    asm("fma.rn.f32x2 %0, %1, %2, %3;" : "=l"(d) : "l"(a), "l"(b), "l"(c));
    return d;
}
__device__ __forceinline__ u64 f2dup(float x) {
    u64 d;
    asm("mov.b64 %0, {%1, %1};" : "=l"(d) : "f"(x));
    return d;
}
__device__ __forceinline__ u32 h2_bits(__half2 h) {
    union { __half2 h; u32 u; } cv;
    cv.h = h;
    return cv.u;
}

// scratch
__device__ __half g_uhat[(size_t)BATCH * NCAPS * INCAPS * DIMC];    // [b][n][c][d] fp16, 64 MB
__device__ float  g_part[(size_t)K1_NCBLK * BATCH * NCAPS * DIMC];  // [cblk][b][n*16+d], 16 MB
__device__ float  g_us2[(size_t)8 * BATCH * NCAPS * DIMC];          // [cs8][b][nd], 1 MB
__device__ float  g_usum[(size_t)BATCH * NCAPS * DIMC];             // 128 KB
__device__ float  g_spart[(size_t)K2_SPLIT * BATCH * NCAPS * DIMC]; // 2 MB

// ---------------------------------------------------------------------------
// Kernel 1: grid (128 cblk, 16 n), 256 threads = 8 warps.
// warp = c, lane = b. ws transposed to [c][i][d]: f32x2 lanes are a d-pair ->
// accumulators come out (d,d+1)-packed, no cross-lane adds.
// bt-PAIRED compute: each W row LDS feeds 2 b-tiles (W LDS halved vs R10).
// ---------------------------------------------------------------------------
__global__ __launch_bounds__(256) void k1_uhat(const float* __restrict__ x,
                                               const float* __restrict__ W) {
    __shared__ float ws[2048];                 // [c_loc][i][d], 8 KB
    __shared__ float xs[32 * XS_STRIDE];       // staging, 16.9 KB
    __shared__ u32   red[8 * RED_STRIDE];      // [c_loc][l*9+dp] half2, 9.25 KB

    const int t = threadIdx.x;
    const int w = t >> 5;        // c-local
    const int l = t & 31;        // b lane
    const int cblk = blockIdx.x;
    const int n    = blockIdx.y;
    const int c0   = cblk * K1_CB;

    // --- load W tile, transposing [c][d][i] -> [c][i][d]
    const float4* Wg4 = (const float4*)W;
    const int wb4 = n * 65536 + c0 * 64;
#pragma unroll
    for (int k = 0; k < 2; k++) {
        int idx4 = t + 256 * k;            // [0,512)
        float4 v = Wg4[wb4 + idx4];
        int flat = idx4 * 4;
        int cl = flat >> 8;
        int d  = (flat >> 4) & 15;
        int i0 = flat & 15;
        ws[cl * 256 + (i0 + 0) * 16 + d] = v.x;
        ws[cl * 256 + (i0 + 1) * 16 + d] = v.y;
        ws[cl * 256 + (i0 + 2) * 16 + d] = v.z;
        ws[cl * 256 + (i0 + 3) * 16 + d] = v.w;
    }

    const float4* xg4 = (const float4*)x;
    uint4* ug = (uint4*)g_uhat;
    const float* wsc = ws + w * 256;

    // preload stage 0 (rows 0..31), coalesced
    float4 P[4];
#pragma unroll
    for (int k = 0; k < 4; k++) {
        int q = t + 256 * k;
        P[k] = xg4[(q >> 5) * 4096 + c0 * 4 + (q & 31)];
    }

    float XA[16], XB[16];

#pragma unroll
    for (int p = 0; p < 2; p++) {
        const int b0 = p * 64;

        // ---- stage half0 (b0..b0+31)
#pragma unroll
        for (int k = 0; k < 4; k++) {
            int q = t + 256 * k;
            *(float4*)&xs[(q >> 5) * XS_STRIDE + (q & 31) * 4] = P[k];
        }
        __syncthreads();                       // xs half0 ready (and ws on p=0)

        // prefetch half1 (overlaps XA copy)
#pragma unroll
        for (int k = 0; k < 4; k++) {
            int q = t + 256 * k;
            P[k] = xg4[(b0 + 32 + (q >> 5)) * 4096 + c0 * 4 + (q & 31)];
        }
        // copy own row -> XA
#pragma unroll
        for (int k = 0; k < 4; k++)
            *(float4*)&XA[k * 4] = *(const float4*)&xs[l * XS_STRIDE + w * 16 + k * 4];
        __syncthreads();                       // XA reads done; xs reusable

        // ---- stage half1 (b0+32..b0+63)
#pragma unroll
        for (int k = 0; k < 4; k++) {
            int q = t + 256 * k;
            *(float4*)&xs[(q >> 5) * XS_STRIDE + (q & 31) * 4] = P[k];
        }
        __syncthreads();                       // xs half1 ready
#pragma unroll
        for (int k = 0; k < 4; k++)
            *(float4*)&XB[k * 4] = *(const float4*)&xs[l * XS_STRIDE + w * 16 + k * 4];

        // ---- paired compute: each W row load feeds both halves
        u64 acc0[8], acc1[8];
#pragma unroll
        for (int dp = 0; dp < 8; dp++) { acc0[dp] = 0ULL; acc1[dp] = 0ULL; }
#pragma unroll
        for (int i = 0; i < 16; i++) {
            ulonglong2 wa = *(const ulonglong2*)&wsc[i * 16 + 0];
            ulonglong2 wb = *(const ulonglong2*)&wsc[i * 16 + 4];
            ulonglong2 wc = *(const ulonglong2*)&wsc[i * 16 + 8];
            ulonglong2 wd = *(const ulonglong2*)&wsc[i * 16 + 12];
            u64 xa = f2dup(XA[i]);
            u64 xb = f2dup(XB[i]);
            acc0[0] = f2fma(xa, wa.x, acc0[0]); acc0[1] = f2fma(xa, wa.y, acc0[1]);
            acc0[2] = f2fma(xa, wb.x, acc0[2]); acc0[3] = f2fma(xa, wb.y, acc0[3]);
            acc0[4] = f2fma(xa, wc.x, acc0[4]); acc0[5] = f2fma(xa, wc.y, acc0[5]);
            acc0[6] = f2fma(xa, wd.x, acc0[6]); acc0[7] = f2fma(xa, wd.y, acc0[7]);
            acc1[0] = f2fma(xb, wa.x, acc1[0]); acc1[1] = f2fma(xb, wa.y, acc1[1]);
            acc1[2] = f2fma(xb, wb.x, acc1[2]); acc1[3] = f2fma(xb, wb.y, acc1[3]);
            acc1[4] = f2fma(xb, wc.x, acc1[4]); acc1[5] = f2fma(xb, wc.y, acc1[5]);
            acc1[6] = f2fma(xb, wd.x, acc1[6]); acc1[7] = f2fma(xb, wd.y, acc1[7]);
        }

        // prefetch next pair half0 (p==0 only; after compute to cap live regs)
        if (p == 0) {
#pragma unroll
            for (int k = 0; k < 4; k++) {
                int q = t + 256 * k;
                P[k] = xg4[(64 + (q >> 5)) * 4096 + c0 * 4 + (q & 31)];
            }
        }

        // ---- drain both halves through red (uhat store + c-partials)
#pragma unroll
        for (int hf = 0; hf < 2; hf++) {
            const int bh = b0 + hf * 32;
            u64* acc = hf ? acc1 : acc0;
#pragma unroll
            for (int dp = 0; dp < 8; dp++) {
                float2 f = *(float2*)&acc[dp];     // (u[2dp], u[2dp+1])
                red[w * RED_STRIDE + l * 9 + dp] = h2_bits(__floats2half2_rn(f.x, f.y));
            }
            __syncthreads();

            // consumer A: coalesced u_hat store (512 uint4, 2/thread)
#pragma unroll
            for (int k = 0; k < 2; k++) {
                int q = t + 256 * k;
                int b_loc = q >> 4;
                int ch    = q & 15;
                int c_loc = ch >> 1;
                int dh    = ch & 1;
                const u32* rp = &red[c_loc * RED_STRIDE + b_loc * 9 + dh * 4];
                uint4 v = make_uint4(rp[0], rp[1], rp[2], rp[3]);
                size_t gi = ((size_t)((bh + b_loc) * 16 + n) * 1024 + c0 + c_loc) * 2 + dh;
                ug[gi] = v;
            }

            // consumer B: c-partials -> g_part
            {
                const int b2 = t >> 3, dp2 = t & 7;
                float s0 = 0.f, s1 = 0.f;
#pragma unroll
                for (int w2 = 0; w2 < 8; w2++) {
                    __half2 hv = *(__half2*)&red[w2 * RED_STRIDE + b2 * 9 + dp2];
                    float2 f = __half22float2(hv);
                    s0 += f.x; s1 += f.y;
                }
                *(float2*)&g_part[cblk * 32768 + (bh + b2) * 256 + n * 16 + dp2 * 2] =
                    make_float2(s0, s1);
            }
            __syncthreads();                   // red free for next half/pair
        }
    }
}

// ---------------------------------------------------------------------------
// k_usum stage 1: grid (128 b, 8), 256 threads: sum 16 cblks each
// ---------------------------------------------------------------------------
__global__ __launch_bounds__(256) void k_usum1() {
    const int t = threadIdx.x, b = blockIdx.x, cs = blockIdx.y;
    const float* p = g_part + (size_t)cs * 16 * 32768 + b * 256 + t;
    float a0 = 0, a1 = 0, a2 = 0, a3 = 0;
#pragma unroll
    for (int k = 0; k < 16; k += 4) {
        a0 += p[(size_t)(k + 0) * 32768];
        a1 += p[(size_t)(k + 1) * 32768];
        a2 += p[(size_t)(k + 2) * 32768];
        a3 += p[(size_t)(k + 3) * 32768];
    }
    g_us2[(size_t)cs * 32768 + b * 256 + t] = (a0 + a1) + (a2 + a3);
}

// ---------------------------------------------------------------------------
// k_usum stage 2: grid 128: sum the 8 partials
// ---------------------------------------------------------------------------
__global__ __launch_bounds__(256) void k_usum2() {
    const int t = threadIdx.x, b = blockIdx.x;
    const float* p = g_us2 + b * 256 + t;
    float a0 = 0, a1 = 0, a2 = 0, a3 = 0;
#pragma unroll
    for (int k = 0; k < 8; k += 4) {
        a0 += p[(size_t)(k + 0) * 32768];
        a1 += p[(size_t)(k + 1) * 32768];
        a2 += p[(size_t)(k + 2) * 32768];
        a3 += p[(size_t)(k + 3) * 32768];
    }
    g_usum[b * 256 + t] = (a0 + a1) + (a2 + a3);
}

// ---------------------------------------------------------------------------
// k2a: grid (128 b, 16 csplit), 256 threads, 2 tiles of 32 c.  (unchanged)
// ---------------------------------------------------------------------------
__global__ __launch_bounds__(256) void k2a_route(const float* __restrict__ Bb) {
    __shared__ uint4 uhs[16 * 97];
    __shared__ float sco[544];
    __shared__ float wbf[544];

    const int t  = threadIdx.x;
    const int b  = blockIdx.x;
    const int cs = blockIdx.y;

    const int sn = t >> 4, scs = t & 15;
    float ur[16];
#pragma unroll
    for (int j = 0; j < 16; j++) ur[j] = g_usum[b * 256 + sn * 16 + j];

    const int asp = t >> 6, an = (t >> 2) & 15, adq = t & 3;
    float sacc0 = 0, sacc1 = 0, sacc2 = 0, sacc3 = 0;

    const uint4* ug = (const uint4*)g_uhat;

    int ld_nn[4], ld_cl[4], ld_dh[4];
#pragma unroll
    for (int k = 0; k < 4; k++) {
        int flat = (t + 256 * k) * 8;
        ld_nn[k] = flat >> 9;
        ld_cl[k] = (flat >> 4) & 31;
        ld_dh[k] = (flat >> 3) & 1;
    }

    uint4 pv[4];
    {
        const int cb = cs * 64;
#pragma unroll
        for (int k = 0; k < 4; k++)
            pv[k] = ug[((size_t)(b * 16 + ld_nn[k]) * 1024 + cb + ld_cl[k]) * 2 + ld_dh[k]];
    }

#pragma unroll
    for (int tile = 0; tile < K2_TILES; tile++) {
        const int cb = cs * 64 + tile * K2_CT;
        __syncthreads();

#pragma unroll
        for (int k = 0; k < 4; k++)
            uhs[ld_nn[k] * 97 + ld_cl[k] * 3 + ld_dh[k]] = pv[k];
        __syncthreads();

        if (tile + 1 < K2_TILES) {
            const int cbn = cb + K2_CT;
#pragma unroll
            for (int k = 0; k < 4; k++)
                pv[k] = ug[((size_t)(b * 16 + ld_nn[k]) * 1024 + cbn + ld_cl[k]) * 2 + ld_dh[k]];
        }

        // --- scores
#pragma unroll
        for (int p = 0; p < 2; p++) {
            int cx = scs + p * 16;
            uint4 ua = uhs[sn * 97 + cx * 3 + 0];
            uint4 ub = uhs[sn * 97 + cx * 3 + 1];
            const __half2* ha = (const __half2*)&ua;
            const __half2* hb = (const __half2*)&ub;
            float dot = 0.f;
#pragma unroll
            for (int j = 0; j < 4; j++) {
                float2 fa = __half22float2(ha[j]);
                float2 fb = __half22float2(hb[j]);
                dot += fa.x * ur[2 * j] + fa.y * ur[2 * j + 1];
                dot += fb.x * ur[8 + 2 * j] + fb.y * ur[9 + 2 * j];
            }
            sco[cx * 17 + sn] = COEF * dot;
        }
        __syncthreads();

        // --- softmax over n + add B
        if (t < 32) {
            int cx = t;
            float v[16];
            float m = -1e30f;
#pragma unroll
            for (int nn = 0; nn < 16; nn++) { v[nn] = sco[cx * 17 + nn]; m = fmaxf(m, v[nn]); }
            float s = 0.f;
#pragma unroll
            for (int nn = 0; nn < 16; nn++) { v[nn] = expf(v[nn] - m); s += v[nn]; }
            float inv = 1.0f / s;
#pragma unroll
            for (int nn = 0; nn < 16; nn++)
                wbf[cx * 17 + nn] = v[nn] * inv + Bb[nn * 1024 + cb + cx];
        }
        __syncthreads();

        // --- weighted accumulate
        const __half2* uh2 = (const __half2*)uhs;
#pragma unroll
        for (int j = 0; j < 8; j++) {
            int cc2 = asp * 8 + j;
            float wv = wbf[cc2 * 17 + an];
            int h2i = (an * 97 + cc2 * 3) * 4 + adq * 2;
            float2 f0 = __half22float2(uh2[h2i]);
            float2 f1 = __half22float2(uh2[h2i + 1]);
            sacc0 += wv * f0.x; sacc1 += wv * f0.y;
            sacc2 += wv * f1.x; sacc3 += wv * f1.y;
        }
    }
    __syncthreads();

    float* spart = (float*)uhs;
    *(float4*)&spart[asp * 256 + an * 16 + adq * 4] = make_float4(sacc0, sacc1, sacc2, sacc3);
    __syncthreads();
    g_spart[cs * 32768 + b * 256 + t] =
        spart[t] + spart[256 + t] + spart[512 + t] + spart[768 + t];
}

// ---------------------------------------------------------------------------
// k2b: reduce 16 csplits, squash, write out
// ---------------------------------------------------------------------------
__global__ __launch_bounds__(256) void k2b_finish(float* __restrict__ out) {
    __shared__ float sfin[256];
    __shared__ float scale[16];
    const int t = threadIdx.x, b = blockIdx.x;

    const float* p = g_spart + b * 256 + t;
    float a0 = 0, a1 = 0, a2 = 0, a3 = 0;
#pragma unroll
    for (int k = 0; k < K2_SPLIT; k += 4) {
        a0 += p[(k + 0) * 32768];
        a1 += p[(k + 1) * 32768];
        a2 += p[(k + 2) * 32768];
        a3 += p[(k + 3) * 32768];
    }
    sfin[t] = (a0 + a1) + (a2 + a3);
    __syncthreads();

    if (t < 16) {
        float sq = 0.f;
#pragma unroll
        for (int d = 0; d < 16; d++) { float z = sfin[t * 16 + d]; sq += z * z; }
        float norm = sqrtf(sq);
        scale[t] = (1.0f - expf(-norm)) * rsqrtf(sq + 1e-8f);
    }
    __syncthreads();

    out[b * 256 + t] = scale[t >> 4] * sfin[t];
}

// ---------------------------------------------------------------------------
extern "C" void kernel_launch(void* const* d_in, const int* in_sizes, int n_in,
                              void* d_out, int out_size) {
    const float* x = (const float*)d_in[0];
    const float* W = (const float*)d_in[1];
    const float* B = (const float*)d_in[2];
    float* out = (float*)d_out;

    k1_uhat<<<dim3(K1_NCBLK, NCAPS), 256>>>(x, W);
    k_usum1<<<dim3(BATCH, 8), 256>>>();
    k_usum2<<<BATCH, 256>>>();
    k2a_route<<<dim3(BATCH, K2_SPLIT), 256>>>(B);
    k2b_finish<<<BATCH, 256>>>(out);
}

// round 14
// speedup vs baseline: 1.8821x; 1.0714x over previous
#include <cuda_runtime.h>
#include <cuda_fp16.h>

// DigitCaps routing:
//   x [128,1024,16], W [1,16,1024,16,16], B [16,1,1024] -> out [128,16,16] (fp32)
// Measured split (R11/R12): k1 ~52us, k2a 29.4us, usum ~5.5us, k2b 5us.
// R14 = R13 design with k1 moved to DYNAMIC shared memory (68KB > 48KB static cap).

#define BATCH  128
#define NCAPS  16
#define INCAPS 1024
#define DIMC   16
#define COEF   0.25f

#define K1_CB     8
#define K1_NCBLK  128
#define K1_NP     4      // n per CTA
#define K2_CT     32
#define K2_SPLIT  16
#define K2_TILES  2      // 1024 / (32*16)

#define RED_STRIDE 289   // u32 row stride for red[.][c_loc][...]
#define XS_STRIDE  132   // float row stride for xs[b_loc][...] (128 + 4 pad)

// k1 dynamic smem layout (bytes)
#define K1_WS_BYTES   (K1_NP * 2048 * 4)            // 32768
#define K1_XS_BYTES   (32 * XS_STRIDE * 4)          // 16896
#define K1_RED_BYTES  (2 * 8 * RED_STRIDE * 4)      // 18496
#define K1_SMEM_BYTES (K1_WS_BYTES + K1_XS_BYTES + K1_RED_BYTES)  // 68160

typedef unsigned long long u64;
typedef unsigned int u32;

__device__ __forceinline__ u64 f2fma(u64 a, u64 b, u64 c) {
    u64 d;
    asm("fma.rn.f32x2 %0, %1, %2, %3;" : "=l"(d) : "l"(a), "l"(b), "l"(c));
    return d;
}
__device__ __forceinline__ u64 f2dup(float x) {
    u64 d;
    asm("mov.b64 %0, {%1, %1};" : "=l"(d) : "f"(x));
    return d;
}
__device__ __forceinline__ u32 h2_bits(__half2 h) {
    union { __half2 h; u32 u; } cv;
    cv.h = h;
    return cv.u;
}

// scratch
__device__ __half g_uhat[(size_t)BATCH * NCAPS * INCAPS * DIMC];    // [b][n][c][d] fp16, 64 MB
__device__ float  g_part[(size_t)K1_NCBLK * BATCH * NCAPS * DIMC];  // [cblk][b][n*16+d], 16 MB
__device__ float  g_us2[(size_t)8 * BATCH * NCAPS * DIMC];          // [cs8][b][nd], 1 MB
__device__ float  g_usum[(size_t)BATCH * NCAPS * DIMC];             // 128 KB
__device__ float  g_spart[(size_t)K2_SPLIT * BATCH * NCAPS * DIMC]; // 2 MB

// ---------------------------------------------------------------------------
// Kernel 1: grid (128 cblk, 4 ngrp), 256 threads = 8 warps, 4 n per CTA.
// warp = c, lane = b. ws [nn][c][i][d] (d-pair f32x2 lanes). The staged x
// pair (XA/XB regs) is reused across all 4 n -> x L2 traffic /4.
// ---------------------------------------------------------------------------
__global__ __launch_bounds__(256, 2) void k1_uhat(const float* __restrict__ x,
                                                  const float* __restrict__ W) {
    extern __shared__ char smem_raw[];
    float* ws  = (float*)smem_raw;                               // [nn][cl][i][d]
    float* xs  = (float*)(smem_raw + K1_WS_BYTES);               // staging
    u32*   red = (u32*)(smem_raw + K1_WS_BYTES + K1_XS_BYTES);   // [hf][cl][l*9+dp]

    const int t = threadIdx.x;
    const int w = t >> 5;        // c-local
    const int l = t & 31;        // b lane
    const int cblk   = blockIdx.x;
    const int n_base = blockIdx.y * K1_NP;
    const int c0     = cblk * K1_CB;

    // --- load 4 W tiles, transposing [c][d][i] -> [nn][c][i][d]
    const float4* Wg4 = (const float4*)W;
#pragma unroll
    for (int k = 0; k < 8; k++) {
        int idx4 = t + 256 * k;            // [0,2048)
        int nn  = idx4 >> 9;
        int rem = idx4 & 511;
        float4 v = Wg4[(size_t)(n_base + nn) * 65536 + c0 * 64 + rem];
        int cl = rem >> 6;
        int d  = (rem >> 2) & 15;
        int i0 = (rem & 3) * 4;
        float* wb = ws + nn * 2048 + cl * 256;
        wb[(i0 + 0) * 16 + d] = v.x;
        wb[(i0 + 1) * 16 + d] = v.y;
        wb[(i0 + 2) * 16 + d] = v.z;
        wb[(i0 + 3) * 16 + d] = v.w;
    }

    const float4* xg4 = (const float4*)x;
    uint4* ug = (uint4*)g_uhat;

    // preload stage 0 (rows 0..31), coalesced
    float4 P[4];
#pragma unroll
    for (int k = 0; k < 4; k++) {
        int q = t + 256 * k;
        P[k] = xg4[(q >> 5) * 4096 + c0 * 4 + (q & 31)];
    }

    float XA[16], XB[16];

#pragma unroll
    for (int p = 0; p < 2; p++) {
        const int b0 = p * 64;

        // ---- stage half0 (b0..b0+31)
#pragma unroll
        for (int k = 0; k < 4; k++) {
            int q = t + 256 * k;
            *(float4*)&xs[(q >> 5) * XS_STRIDE + (q & 31) * 4] = P[k];
        }
        __syncthreads();                       // xs half0 (and ws on p=0) ready

        // prefetch half1
#pragma unroll
        for (int k = 0; k < 4; k++) {
            int q = t + 256 * k;
            P[k] = xg4[(b0 + 32 + (q >> 5)) * 4096 + c0 * 4 + (q & 31)];
        }
#pragma unroll
        for (int k = 0; k < 4; k++)
            *(float4*)&XA[k * 4] = *(const float4*)&xs[l * XS_STRIDE + w * 16 + k * 4];
        __syncthreads();                       // XA reads done; xs reusable

        // ---- stage half1 (b0+32..b0+63)
#pragma unroll
        for (int k = 0; k < 4; k++) {
            int q = t + 256 * k;
            *(float4*)&xs[(q >> 5) * XS_STRIDE + (q & 31) * 4] = P[k];
        }
        __syncthreads();                       // xs half1 ready
#pragma unroll
        for (int k = 0; k < 4; k++)
            *(float4*)&XB[k * 4] = *(const float4*)&xs[l * XS_STRIDE + w * 16 + k * 4];

        // ---- n loop: reuse XA/XB for 4 n
#pragma unroll
        for (int nn = 0; nn < K1_NP; nn++) {
            const float* wsc = ws + nn * 2048 + w * 256;
            const int n = n_base + nn;

            u64 acc0[8], acc1[8];
#pragma unroll
            for (int dp = 0; dp < 8; dp++) { acc0[dp] = 0ULL; acc1[dp] = 0ULL; }
#pragma unroll
            for (int i = 0; i < 16; i++) {
                ulonglong2 wa = *(const ulonglong2*)&wsc[i * 16 + 0];
                ulonglong2 wb2 = *(const ulonglong2*)&wsc[i * 16 + 4];
                ulonglong2 wc = *(const ulonglong2*)&wsc[i * 16 + 8];
                ulonglong2 wd = *(const ulonglong2*)&wsc[i * 16 + 12];
                u64 xa = f2dup(XA[i]);
                u64 xb = f2dup(XB[i]);
                acc0[0] = f2fma(xa, wa.x, acc0[0]); acc0[1] = f2fma(xa, wa.y, acc0[1]);
                acc0[2] = f2fma(xa, wb2.x, acc0[2]); acc0[3] = f2fma(xa, wb2.y, acc0[3]);
                acc0[4] = f2fma(xa, wc.x, acc0[4]); acc0[5] = f2fma(xa, wc.y, acc0[5]);
                acc0[6] = f2fma(xa, wd.x, acc0[6]); acc0[7] = f2fma(xa, wd.y, acc0[7]);
                acc1[0] = f2fma(xb, wa.x, acc1[0]); acc1[1] = f2fma(xb, wa.y, acc1[1]);
                acc1[2] = f2fma(xb, wb2.x, acc1[2]); acc1[3] = f2fma(xb, wb2.y, acc1[3]);
                acc1[4] = f2fma(xb, wc.x, acc1[4]); acc1[5] = f2fma(xb, wc.y, acc1[5]);
                acc1[6] = f2fma(xb, wd.x, acc1[6]); acc1[7] = f2fma(xb, wd.y, acc1[7]);
            }

            // prefetch next pair half0 (once, early in the nn loop)
            if (p == 0 && nn == 0) {
#pragma unroll
                for (int k = 0; k < 4; k++) {
                    int q = t + 256 * k;
                    P[k] = xg4[(64 + (q >> 5)) * 4096 + c0 * 4 + (q & 31)];
                }
            }

            // ---- drain both halves through red
#pragma unroll
            for (int dp = 0; dp < 8; dp++) {
                float2 f0 = *(float2*)&acc0[dp];
                float2 f1 = *(float2*)&acc1[dp];
                red[(0 * 8 + w) * RED_STRIDE + l * 9 + dp] =
                    h2_bits(__floats2half2_rn(f0.x, f0.y));
                red[(1 * 8 + w) * RED_STRIDE + l * 9 + dp] =
                    h2_bits(__floats2half2_rn(f1.x, f1.y));
            }
            __syncthreads();

            // consumer A: coalesced u_hat store (1024 uint4, 4/thread)
#pragma unroll
            for (int k = 0; k < 4; k++) {
                int q = t + 256 * k;            // [0,1024)
                int hf = q >> 9;
                int qq = q & 511;
                int b_loc = qq >> 4;
                int ch    = qq & 15;
                int c_loc = ch >> 1;
                int dh    = ch & 1;
                const u32* rp = &red[(hf * 8 + c_loc) * RED_STRIDE + b_loc * 9 + dh * 4];
                uint4 v = make_uint4(rp[0], rp[1], rp[2], rp[3]);
                size_t gi = ((size_t)((b0 + hf * 32 + b_loc) * 16 + n) * 1024
                             + c0 + c_loc) * 2 + dh;
                ug[gi] = v;
            }

            // consumer B: c-partials -> g_part (both halves)
            {
                const int b2 = t >> 3, dp2 = t & 7;
#pragma unroll
                for (int hh = 0; hh < 2; hh++) {
                    float s0 = 0.f, s1 = 0.f;
#pragma unroll
                    for (int w2 = 0; w2 < 8; w2++) {
                        __half2 hv = *(__half2*)&red[(hh * 8 + w2) * RED_STRIDE + b2 * 9 + dp2];
                        float2 f = __half22float2(hv);
                        s0 += f.x; s1 += f.y;
                    }
                    *(float2*)&g_part[cblk * 32768 + (b0 + hh * 32 + b2) * 256
                                      + n * 16 + dp2 * 2] = make_float2(s0, s1);
                }
            }
            __syncthreads();                   // red free; also orders xs reuse
        }
    }
}

// ---------------------------------------------------------------------------
// k_usum stage 1: grid (128 b, 8), 256 threads: sum 16 cblks each
// ---------------------------------------------------------------------------
__global__ __launch_bounds__(256) void k_usum1() {
    const int t = threadIdx.x, b = blockIdx.x, cs = blockIdx.y;
    const float* p = g_part + (size_t)cs * 16 * 32768 + b * 256 + t;
    float a0 = 0, a1 = 0, a2 = 0, a3 = 0;
#pragma unroll
    for (int k = 0; k < 16; k += 4) {
        a0 += p[(size_t)(k + 0) * 32768];
        a1 += p[(size_t)(k + 1) * 32768];
        a2 += p[(size_t)(k + 2) * 32768];
        a3 += p[(size_t)(k + 3) * 32768];
    }
    g_us2[(size_t)cs * 32768 + b * 256 + t] = (a0 + a1) + (a2 + a3);
}

// ---------------------------------------------------------------------------
// k_usum stage 2: grid 128: sum the 8 partials
// ---------------------------------------------------------------------------
__global__ __launch_bounds__(256) void k_usum2() {
    const int t = threadIdx.x, b = blockIdx.x;
    const float* p = g_us2 + b * 256 + t;
    float a0 = 0, a1 = 0, a2 = 0, a3 = 0;
#pragma unroll
    for (int k = 0; k < 8; k += 4) {
        a0 += p[(size_t)(k + 0) * 32768];
        a1 += p[(size_t)(k + 1) * 32768];
        a2 += p[(size_t)(k + 2) * 32768];
        a3 += p[(size_t)(k + 3) * 32768];
    }
    g_usum[b * 256 + t] = (a0 + a1) + (a2 + a3);
}

// ---------------------------------------------------------------------------
// k2a: grid (128 b, 16 csplit), 256 threads, 2 tiles of 32 c.
// Accumulate loads widened to LDS.64 (uint2).
// ---------------------------------------------------------------------------
__global__ __launch_bounds__(256) void k2a_route(const float* __restrict__ Bb) {
    __shared__ uint4 uhs[16 * 97];
    __shared__ float sco[544];
    __shared__ float wbf[544];

    const int t  = threadIdx.x;
    const int b  = blockIdx.x;
    const int cs = blockIdx.y;

    const int sn = t >> 4, scs = t & 15;
    float ur[16];
#pragma unroll
    for (int j = 0; j < 16; j++) ur[j] = g_usum[b * 256 + sn * 16 + j];

    const int asp = t >> 6, an = (t >> 2) & 15, adq = t & 3;
    float sacc0 = 0, sacc1 = 0, sacc2 = 0, sacc3 = 0;

    const uint4* ug = (const uint4*)g_uhat;

    int ld_nn[4], ld_cl[4], ld_dh[4];
#pragma unroll
    for (int k = 0; k < 4; k++) {
        int flat = (t + 256 * k) * 8;
        ld_nn[k] = flat >> 9;
        ld_cl[k] = (flat >> 4) & 31;
        ld_dh[k] = (flat >> 3) & 1;
    }

    uint4 pv[4];
    {
        const int cb = cs * 64;
#pragma unroll
        for (int k = 0; k < 4; k++)
            pv[k] = ug[((size_t)(b * 16 + ld_nn[k]) * 1024 + cb + ld_cl[k]) * 2 + ld_dh[k]];
    }

#pragma unroll
    for (int tile = 0; tile < K2_TILES; tile++) {
        const int cb = cs * 64 + tile * K2_CT;
        __syncthreads();

#pragma unroll
        for (int k = 0; k < 4; k++)
            uhs[ld_nn[k] * 97 + ld_cl[k] * 3 + ld_dh[k]] = pv[k];
        __syncthreads();

        if (tile + 1 < K2_TILES) {
            const int cbn = cb + K2_CT;
#pragma unroll
            for (int k = 0; k < 4; k++)
                pv[k] = ug[((size_t)(b * 16 + ld_nn[k]) * 1024 + cbn + ld_cl[k]) * 2 + ld_dh[k]];
        }

        // --- scores
#pragma unroll
        for (int p = 0; p < 2; p++) {
            int cx = scs + p * 16;
            uint4 ua = uhs[sn * 97 + cx * 3 + 0];
            uint4 ub = uhs[sn * 97 + cx * 3 + 1];
            const __half2* ha = (const __half2*)&ua;
            const __half2* hb = (const __half2*)&ub;
            float dot = 0.f;
#pragma unroll
            for (int j = 0; j < 4; j++) {
                float2 fa = __half22float2(ha[j]);
                float2 fb = __half22float2(hb[j]);
                dot += fa.x * ur[2 * j] + fa.y * ur[2 * j + 1];
                dot += fb.x * ur[8 + 2 * j] + fb.y * ur[9 + 2 * j];
            }
            sco[cx * 17 + sn] = COEF * dot;
        }
        __syncthreads();

        // --- softmax over n + add B
        if (t < 32) {
            int cx = t;
            float v[16];
            float m = -1e30f;
#pragma unroll
            for (int nn = 0; nn < 16; nn++) { v[nn] = sco[cx * 17 + nn]; m = fmaxf(m, v[nn]); }
            float s = 0.f;
#pragma unroll
            for (int nn = 0; nn < 16; nn++) { v[nn] = expf(v[nn] - m); s += v[nn]; }
            float inv = 1.0f / s;
#pragma unroll
            for (int nn = 0; nn < 16; nn++)
                wbf[cx * 17 + nn] = v[nn] * inv + Bb[nn * 1024 + cb + cx];
        }
        __syncthreads();

        // --- weighted accumulate (LDS.64)
        const uint2* uh64 = (const uint2*)uhs;
#pragma unroll
        for (int j = 0; j < 8; j++) {
            int cc2 = asp * 8 + j;
            float wv = wbf[cc2 * 17 + an];
            uint2 uv = uh64[(an * 97 + cc2 * 3) * 2 + adq];
            float2 f0 = __half22float2(*(__half2*)&uv.x);
            float2 f1 = __half22float2(*(__half2*)&uv.y);
            sacc0 += wv * f0.x; sacc1 += wv * f0.y;
            sacc2 += wv * f1.x; sacc3 += wv * f1.y;
        }
    }
    __syncthreads();

    float* spart = (float*)uhs;
    *(float4*)&spart[asp * 256 + an * 16 + adq * 4] = make_float4(sacc0, sacc1, sacc2, sacc3);
    __syncthreads();
    g_spart[cs * 32768 + b * 256 + t] =
        spart[t] + spart[256 + t] + spart[512 + t] + spart[768 + t];
}

// ---------------------------------------------------------------------------
// k2b: reduce 16 csplits, squash, write out
// ---------------------------------------------------------------------------
__global__ __launch_bounds__(256) void k2b_finish(float* __restrict__ out) {
    __shared__ float sfin[256];
    __shared__ float scale[16];
    const int t = threadIdx.x, b = blockIdx.x;

    const float* p = g_spart + b * 256 + t;
    float a0 = 0, a1 = 0, a2 = 0, a3 = 0;
#pragma unroll
    for (int k = 0; k < K2_SPLIT; k += 4) {
        a0 += p[(k + 0) * 32768];
        a1 += p[(k + 1) * 32768];
        a2 += p[(k + 2) * 32768];
        a3 += p[(k + 3) * 32768];
    }
    sfin[t] = (a0 + a1) + (a2 + a3);
    __syncthreads();

    if (t < 16) {
        float sq = 0.f;
#pragma unroll
        for (int d = 0; d < 16; d++) { float z = sfin[t * 16 + d]; sq += z * z; }
        float norm = sqrtf(sq);
        scale[t] = (1.0f - expf(-norm)) * rsqrtf(sq + 1e-8f);
    }
    __syncthreads();

    out[b * 256 + t] = scale[t >> 4] * sfin[t];
}

// ---------------------------------------------------------------------------
extern "C" void kernel_launch(void* const* d_in, const int* in_sizes, int n_in,
                              void* d_out, int out_size) {
    const float* x = (const float*)d_in[0];
    const float* W = (const float*)d_in[1];
    const float* B = (const float*)d_in[2];
    float* out = (float*)d_out;

    // Allow >48KB dynamic smem for k1 (device-level attribute; no allocation).
    cudaFuncSetAttribute(k1_uhat, cudaFuncAttributeMaxDynamicSharedMemorySize,
                         K1_SMEM_BYTES);

    k1_uhat<<<dim3(K1_NCBLK, K1_NP), 256, K1_SMEM_BYTES>>>(x, W);
    k_usum1<<<dim3(BATCH, 8), 256>>>();
    k_usum2<<<BATCH, 256>>>();
    k2a_route<<<dim3(BATCH, K2_SPLIT), 256>>>(B);
    k2b_finish<<<BATCH, 256>>>(out);
}